// round 2
// baseline (speedup 1.0000x reference)
#include <cuda_runtime.h>
#include <math.h>
#include <stdint.h>

#define N_NODES 10000
#define N_EDGES 160000
#define NF 128
#define NB 20
#define NLAYERS 3
#define CUTOFF_R 5.0f

// ---------------- device scratch (no allocations allowed) ----------------
__device__ float g_dist[(size_t)N_EDGES * NB];          // rbf*fc  (E,20)
__device__ float g_dir[(size_t)N_EDGES * 3];            // unit dirs (E,3)
__device__ float g_h[(size_t)N_NODES * NF];             // h (N,F)
__device__ float g_msg[(size_t)N_EDGES * NF];           // msg (E,F)
__device__ float g_a[(size_t)N_EDGES * NF];             // silu intermediate / node tmp
__device__ float g_p1[(size_t)N_EDGES * NF];            // e1 scalar part; reused as g = force@eu_W
__device__ float g_p2[(size_t)N_EDGES * NF];            // e2 scalar part
__device__ float g_fdelta[(size_t)N_NODES * 3 * NF];    // per-layer force delta
__device__ float g_force_fb[(size_t)N_NODES * 3 * NF];  // fallback force buffer

// ---------------- init: atom = node_emb[z] ----------------
__global__ void init_atom_k(const int* __restrict__ z, const float* __restrict__ emb,
                            float* __restrict__ atom)
{
    int idx = blockIdx.x * blockDim.x + threadIdx.x;   // N*128
    int n = idx >> 7, f = idx & 127;
    atom[idx] = emb[(size_t)z[n] * NF + f];
}

// ---------------- edge embedding ----------------
__global__ void edge_embed_k(const float* __restrict__ pos, const int* __restrict__ ei,
                             float* __restrict__ dist, float* __restrict__ dir)
{
    int e = blockIdx.x * blockDim.x + threadIdx.x;
    if (e >= N_EDGES) return;
    int i = ei[e], j = ei[N_EDGES + e];
    float dx = pos[j*3+0] - pos[i*3+0];
    float dy = pos[j*3+1] - pos[i*3+1];
    float dz = pos[j*3+2] - pos[i*3+2];
    float d = sqrtf(dx*dx + dy*dy + dz*dz + 1e-12f);
    float inv = 1.0f / d;
    dir[e*3+0] = dx*inv; dir[e*3+1] = dy*inv; dir[e*3+2] = dz*inv;
    float fc = (d < CUTOFF_R) ? 0.5f * (cosf(3.14159265358979323846f * d / CUTOFF_R) + 1.0f) : 0.0f;
    const float inv_w = 1.0f / (CUTOFF_R / NB);  // width = 0.25
    #pragma unroll
    for (int b = 0; b < NB; b++) {
        float c = CUTOFF_R * (float)b / (float)(NB - 1);
        float t = (d - c) * inv_w;
        dist[(size_t)e*NB + b] = expf(-t*t) * fc;
    }
}

// ---------------- generic M x 128 x 128 GEMM, optional bias + silu ----------------
// block: 256 thr (16x16), tile 64x128, full K=128 in smem. 4x8 microtile.
template<bool SILU, bool BIAS>
__global__ void gemm128_k(const float* __restrict__ A, const float* __restrict__ B,
                          const float* __restrict__ bias, float* __restrict__ C, int M)
{
    extern __shared__ float sm[];
    float* As = sm;              // [64][132]
    float* Bs = sm + 64 * 132;   // [128][132]
    const int tx = threadIdx.x, ty = threadIdx.y;
    const int tid = ty * 16 + tx;
    const int m0 = blockIdx.x * 64;

    const float4* B4 = reinterpret_cast<const float4*>(B);
    #pragma unroll
    for (int q = 0; q < 16; q++) {
        int lin = q * 256 + tid;          // 0..4095
        int r = lin >> 5, c4 = lin & 31;
        float4 v = B4[lin];
        *reinterpret_cast<float4*>(&Bs[r*132 + c4*4]) = v;
    }
    const float4* A4 = reinterpret_cast<const float4*>(A);
    #pragma unroll
    for (int q = 0; q < 8; q++) {
        int lin = q * 256 + tid;          // 0..2047
        int r = lin >> 5, c4 = lin & 31;
        float4 v = make_float4(0.f, 0.f, 0.f, 0.f);
        if (m0 + r < M) v = A4[(size_t)(m0 + r) * 32 + c4];
        *reinterpret_cast<float4*>(&As[r*132 + c4*4]) = v;
    }
    __syncthreads();

    float acc[4][8];
    #pragma unroll
    for (int i = 0; i < 4; i++)
        #pragma unroll
        for (int jj = 0; jj < 8; jj++) acc[i][jj] = 0.f;

    #pragma unroll 8
    for (int k = 0; k < 128; k++) {
        float aa[4];
        #pragma unroll
        for (int i = 0; i < 4; i++) aa[i] = As[(ty*4 + i)*132 + k];
        float4 b0 = *reinterpret_cast<const float4*>(&Bs[k*132 + tx*8]);
        float4 b1 = *reinterpret_cast<const float4*>(&Bs[k*132 + tx*8 + 4]);
        float bb[8] = {b0.x, b0.y, b0.z, b0.w, b1.x, b1.y, b1.z, b1.w};
        #pragma unroll
        for (int i = 0; i < 4; i++)
            #pragma unroll
            for (int jj = 0; jj < 8; jj++)
                acc[i][jj] = fmaf(aa[i], bb[jj], acc[i][jj]);
    }

    float bvals[8];
    if (BIAS) {
        #pragma unroll
        for (int jj = 0; jj < 8; jj++) bvals[jj] = bias[tx*8 + jj];
    }
    #pragma unroll
    for (int i = 0; i < 4; i++) {
        int row = m0 + ty*4 + i;
        if (row < M) {
            float out[8];
            #pragma unroll
            for (int jj = 0; jj < 8; jj++) {
                float v = acc[i][jj];
                if (BIAS) v += bvals[jj];
                if (SILU) v = v / (1.0f + expf(-v));
                out[jj] = v;
            }
            float4* Cp = reinterpret_cast<float4*>(&C[(size_t)row * NF + tx*8]);
            Cp[0] = make_float4(out[0], out[1], out[2], out[3]);
            Cp[1] = make_float4(out[4], out[5], out[6], out[7]);
        }
    }
}

// ---------------- msg = (dist @ me_W) * h[i] * h[j]; atom += segsum(msg, i) ----------------
// 128 thr/block, 32 edges/block (E % 32 == 0)
__global__ void msg_k(const float* __restrict__ h, const float* __restrict__ dist,
                      const int* __restrict__ ei, const float* __restrict__ meW,
                      float* __restrict__ msg, float* __restrict__ atom)
{
    __shared__ float sW[NB * NF];
    __shared__ float sd[32 * NB];
    int f = threadIdx.x;
    #pragma unroll
    for (int b = 0; b < NB; b++) sW[b*NF + f] = meW[b*NF + f];
    int e0 = blockIdx.x * 32;
    for (int q = f; q < 32 * NB; q += NF) sd[q] = dist[(size_t)e0 * NB + q];
    __syncthreads();
    #pragma unroll 2
    for (int t = 0; t < 32; t++) {
        int e = e0 + t;
        int i = ei[e], j = ei[N_EDGES + e];
        float me = 0.f;
        #pragma unroll
        for (int b = 0; b < NB; b++) me = fmaf(sd[t*NB + b], sW[b*NF + f], me);
        float m = me * h[(size_t)i*NF + f] * h[(size_t)j*NF + f];
        msg[(size_t)e*NF + f] = m;
        atomicAdd(&atom[(size_t)i*NF + f], m);
    }
}

// ---------------- fdelta += segsum(p1*dir + p2*force[j], i) ----------------
// 128 thr/block, 8 edges/block (E % 8 == 0)
__global__ void scatter_force_k(const float* __restrict__ p1, const float* __restrict__ p2,
                                const float* __restrict__ dir, const float* __restrict__ force,
                                const int* __restrict__ ei, float* __restrict__ fdelta)
{
    int f = threadIdx.x;
    int e0 = blockIdx.x * 8;
    for (int t = 0; t < 8; t++) {
        int e = e0 + t;
        int i = ei[e], j = ei[N_EDGES + e];
        float v1 = p1[(size_t)e*NF + f];
        float v2 = p2[(size_t)e*NF + f];
        float dx = dir[e*3+0], dy = dir[e*3+1], dz = dir[e*3+2];
        const float* fj = &force[(size_t)j * 3 * NF];
        float* fd = &fdelta[(size_t)i * 3 * NF];
        atomicAdd(&fd[0*NF + f], fmaf(v1, dx, v2 * fj[0*NF + f]));
        atomicAdd(&fd[1*NF + f], fmaf(v1, dy, v2 * fj[1*NF + f]));
        atomicAdd(&fd[2*NF + f], fmaf(v1, dz, v2 * fj[2*NF + f]));
    }
}

// ---------------- force += fdelta; fdelta = 0 ----------------
__global__ void force_update_k(float* __restrict__ force, float* __restrict__ fdelta)
{
    int idx = blockIdx.x * blockDim.x + threadIdx.x;   // N*3*128
    force[idx] += fdelta[idx];
    fdelta[idx] = 0.f;
}

// ---------------- atom += sum_d force[n,d,:] * g[n,d,:] ----------------
__global__ void atom_update_k(float* __restrict__ atom, const float* __restrict__ force,
                              const float* __restrict__ g)
{
    int idx = blockIdx.x * blockDim.x + threadIdx.x;   // N*128
    int n = idx >> 7, f = idx & 127;
    size_t base = (size_t)n * 3 * NF + f;
    float s = force[base]        * g[base]
            + force[base + NF]   * g[base + NF]
            + force[base + 2*NF] * g[base + 2*NF];
    atom[idx] += s;
}

// ---------------- host ----------------
extern "C" void kernel_launch(void* const* d_in, const int* in_sizes, int n_in,
                              void* d_out, int out_size)
{
    const int*   z        = (const int*)  d_in[0];
    const float* pos      = (const float*)d_in[1];
    // d_in[2] = cell, d_in[3] = batch : unused (disp == identity in forward)
    const int*   ei       = (const int*)  d_in[4];
    const float* node_emb = (const float*)d_in[5];
    const float* mnp_W1   = (const float*)d_in[6];
    const float* mnp_b1   = (const float*)d_in[7];
    const float* mnp_W2   = (const float*)d_in[8];
    const float* mnp_b2   = (const float*)d_in[9];
    const float* me_W     = (const float*)d_in[10];
    const float* em1_W1   = (const float*)d_in[11];
    const float* em1_W2   = (const float*)d_in[12];
    const float* em2_W1   = (const float*)d_in[13];
    const float* em2_W2   = (const float*)d_in[14];
    const float* eu_W     = (const float*)d_in[15];

    float* atom  = (float*)d_out;
    float* force;

    float *dist, *dir, *h, *msg, *abuf, *p1, *p2, *fdelta, *force_fb;
    cudaGetSymbolAddress((void**)&dist,     g_dist);
    cudaGetSymbolAddress((void**)&dir,      g_dir);
    cudaGetSymbolAddress((void**)&h,        g_h);
    cudaGetSymbolAddress((void**)&msg,      g_msg);
    cudaGetSymbolAddress((void**)&abuf,     g_a);
    cudaGetSymbolAddress((void**)&p1,       g_p1);
    cudaGetSymbolAddress((void**)&p2,       g_p2);
    cudaGetSymbolAddress((void**)&fdelta,   g_fdelta);
    cudaGetSymbolAddress((void**)&force_fb, g_force_fb);

    // force lives in d_out if the harness concatenated (atom, force); else fallback scratch
    if (out_size >= N_NODES * (NF + 3 * NF)) force = atom + (size_t)N_NODES * NF;
    else                                     force = force_fb;

    const int SMEM = (64 + 128) * 132 * (int)sizeof(float);   // 101376 B
    cudaFuncSetAttribute(gemm128_k<true,  true >, cudaFuncAttributeMaxDynamicSharedMemorySize, SMEM);
    cudaFuncSetAttribute(gemm128_k<false, true >, cudaFuncAttributeMaxDynamicSharedMemorySize, SMEM);
    cudaFuncSetAttribute(gemm128_k<true,  false>, cudaFuncAttributeMaxDynamicSharedMemorySize, SMEM);
    cudaFuncSetAttribute(gemm128_k<false, false>, cudaFuncAttributeMaxDynamicSharedMemorySize, SMEM);

    dim3 gblk(16, 16);

    cudaMemsetAsync(force,  0, (size_t)N_NODES * 3 * NF * sizeof(float), 0);
    cudaMemsetAsync(fdelta, 0, (size_t)N_NODES * 3 * NF * sizeof(float), 0);

    init_atom_k<<<(N_NODES * NF) / 256, 256>>>(z, node_emb, atom);
    edge_embed_k<<<(N_EDGES + 255) / 256, 256>>>(pos, ei, dist, dir);

    for (int l = 0; l < NLAYERS; l++) {
        const float* W1 = mnp_W1 + (size_t)l * NF * NF;
        const float* b1 = mnp_b1 + (size_t)l * NF;
        const float* W2 = mnp_W2 + (size_t)l * NF * NF;
        const float* b2 = mnp_b2 + (size_t)l * NF;
        const float* mW = me_W   + (size_t)l * NB * NF;
        const float* e11 = em1_W1 + (size_t)l * NF * NF;
        const float* e12 = em1_W2 + (size_t)l * NF * NF;
        const float* e21 = em2_W1 + (size_t)l * NF * NF;
        const float* e22 = em2_W2 + (size_t)l * NF * NF;
        const float* euW = eu_W   + (size_t)l * NF * NF;

        // h = silu(atom @ W1 + b1) @ W2 + b2
        gemm128_k<true,  true ><<<(N_NODES + 63) / 64, gblk, SMEM>>>(atom, W1, b1, abuf, N_NODES);
        gemm128_k<false, true ><<<(N_NODES + 63) / 64, gblk, SMEM>>>(abuf, W2, b2, h,    N_NODES);

        // msg + atom segsum
        msg_k<<<N_EDGES / 32, NF>>>(h, dist, ei, mW, msg, atom);

        // p1 = silu(msg@e11)@e12 ; p2 = silu(msg@e21)@e22
        gemm128_k<true,  false><<<N_EDGES / 64, gblk, SMEM>>>(msg,  e11, nullptr, abuf, N_EDGES);
        gemm128_k<false, false><<<N_EDGES / 64, gblk, SMEM>>>(abuf, e12, nullptr, p1,   N_EDGES);
        gemm128_k<true,  false><<<N_EDGES / 64, gblk, SMEM>>>(msg,  e21, nullptr, abuf, N_EDGES);
        gemm128_k<false, false><<<N_EDGES / 64, gblk, SMEM>>>(abuf, e22, nullptr, p2,   N_EDGES);

        // force delta scatter, then force update (+ fdelta re-zero)
        scatter_force_k<<<N_EDGES / 8, NF>>>(p1, p2, dir, force, ei, fdelta);
        force_update_k<<<(N_NODES * 3 * NF) / 256, 256>>>(force, fdelta);

        // g = force @ eu_W  (rows = N*3); reuse p1 as g
        gemm128_k<false, false><<<(N_NODES * 3 + 63) / 64, gblk, SMEM>>>(force, euW, nullptr, p1, N_NODES * 3);
        atom_update_k<<<(N_NODES * NF) / 256, 256>>>(atom, force, p1);
    }
}

// round 5
// speedup vs baseline: 1.0884x; 1.0884x over previous
#include <cuda_runtime.h>
#include <cuda_bf16.h>
#include <math.h>
#include <stdint.h>

#define N_NODES 10000
#define N_EDGES 160000
#define NF 128
#define NB 20
#define NLAYERS 3
#define CUTOFF_R 5.0f

// ---------------- device scratch (no allocations allowed) ----------------
__device__ float g_dist[(size_t)N_EDGES * NB];
__device__ float g_dir[(size_t)N_EDGES * 3];
__device__ float g_h[(size_t)N_NODES * NF];
__device__ float g_msg[(size_t)N_EDGES * NF];
__device__ float g_a[(size_t)N_EDGES * NF];
__device__ float g_p1[(size_t)N_EDGES * NF];
__device__ float g_p2[(size_t)N_EDGES * NF];
__device__ float g_fdelta[(size_t)N_NODES * 3 * NF];
__device__ float g_force_fb[(size_t)N_NODES * 3 * NF];

// ============================ warp MMA helpers ============================
__device__ __forceinline__ uint32_t smem_u32(const void* p) {
    uint32_t a;
    asm("{ .reg .u64 t; cvta.to.shared.u64 t, %1; cvt.u32.u64 %0, t; }" : "=r"(a) : "l"(p));
    return a;
}
__device__ __forceinline__ void ldsm_x4(uint32_t* r, uint32_t addr) {
    asm volatile("ldmatrix.sync.aligned.m8n8.x4.shared.b16 {%0,%1,%2,%3}, [%4];"
                 : "=r"(r[0]), "=r"(r[1]), "=r"(r[2]), "=r"(r[3]) : "r"(addr));
}
__device__ __forceinline__ void mma_bf16(float* d, const uint32_t* a, uint32_t b0, uint32_t b1) {
    asm volatile(
        "mma.sync.aligned.m16n8k16.row.col.f32.bf16.bf16.f32 "
        "{%0,%1,%2,%3},{%4,%5,%6,%7},{%8,%9},{%0,%1,%2,%3};"
        : "+f"(d[0]), "+f"(d[1]), "+f"(d[2]), "+f"(d[3])
        : "r"(a[0]), "r"(a[1]), "r"(a[2]), "r"(a[3]), "r"(b0), "r"(b1));
}

// ============================ HMMA GEMM ============================
// C[M,128] = A[M,128] @ W[128,128] (+bias)(+silu); fp32 I/O, bf16x3 internally.
// 256 threads (8 warps); tile 128x128; warp = 32 rows x 64 cols.
// smem: Ahi/Alo [128][136] bf16 (row-major, 272B stride), Bt hi/lo [128][136] (Bt[n][k]=W[k][n]).
#define LDA 136
#define A_BYTES (128 * LDA * 2)            // 34816
#define SM_AHI  0
#define SM_ALO  (A_BYTES)
#define SM_BHI  (2 * A_BYTES)
#define SM_BLO  (3 * A_BYTES)
#define SM_BIAS (4 * A_BYTES)
#define SM_TOTAL (4 * A_BYTES + 512)       // 139776

template<bool SILU, bool BIAS>
__global__ void __launch_bounds__(256) mma_gemm_k(
    const float* __restrict__ A, const float* __restrict__ W,
    const float* __restrict__ bias, float* __restrict__ C, int M)
{
    extern __shared__ char sm[];
    const uint32_t smb = smem_u32(sm);
    const int tid  = threadIdx.x;
    const int wid  = tid >> 5;
    const int lane = tid & 31;
    const int m0   = blockIdx.x * 128;
    const int warp_m = wid >> 1;          // 0..3  -> rows warp_m*32..+32
    const int warp_n = wid & 1;           // 0..1  -> cols warp_n*64..+64

    if (BIAS && tid < 128) ((float*)(sm + SM_BIAS))[tid] = bias[tid];

    // ---- load W[k][n], store transposed Bt[n][k] split hi/lo ----
    {
        const float4* W4 = reinterpret_cast<const float4*>(W);
        #pragma unroll 4
        for (int q = 0; q < 16; q++) {
            int lin = q * 256 + tid;               // 4096 float4
            int k = lin >> 5, n4 = (lin & 31) << 2;
            float4 v = W4[lin];
            float vv[4] = {v.x, v.y, v.z, v.w};
            #pragma unroll
            for (int t = 0; t < 4; t++) {
                __nv_bfloat16 hb = __float2bfloat16(vv[t]);
                __nv_bfloat16 lb = __float2bfloat16(vv[t] - __bfloat162float(hb));
                size_t off = (size_t)(n4 + t) * LDA + k;
                *(__nv_bfloat16*)(sm + SM_BHI + off * 2) = hb;
                *(__nv_bfloat16*)(sm + SM_BLO + off * 2) = lb;
            }
        }
    }
    // ---- load A tile rows, split hi/lo (packed 4-elem stores) ----
    {
        const float4* A4 = reinterpret_cast<const float4*>(A);
        #pragma unroll 4
        for (int q = 0; q < 16; q++) {
            int lin = q * 256 + tid;               // 4096 float4
            int row = lin >> 5, c4 = (lin & 31) << 2;
            float4 v = make_float4(0.f, 0.f, 0.f, 0.f);
            if (m0 + row < M) v = A4[(size_t)(m0 + row) * 32 + (c4 >> 2)];
            float vv[4] = {v.x, v.y, v.z, v.w};
            uint16_t h[4], l[4];
            #pragma unroll
            for (int t = 0; t < 4; t++) {
                __nv_bfloat16 hb = __float2bfloat16(vv[t]);
                __nv_bfloat16 lb = __float2bfloat16(vv[t] - __bfloat162float(hb));
                h[t] = __bfloat16_as_ushort(hb);
                l[t] = __bfloat16_as_ushort(lb);
            }
            size_t boff = ((size_t)row * LDA + c4) * 2;   // 8B aligned
            *(uint2*)(sm + SM_AHI + boff) = make_uint2((uint32_t)h[0] | ((uint32_t)h[1] << 16),
                                                       (uint32_t)h[2] | ((uint32_t)h[3] << 16));
            *(uint2*)(sm + SM_ALO + boff) = make_uint2((uint32_t)l[0] | ((uint32_t)l[1] << 16),
                                                       (uint32_t)l[2] | ((uint32_t)l[3] << 16));
        }
    }
    __syncthreads();

    // ---- fragment base addresses ----
    // A ldmatrix.x4 (16x16): lanes 0-15 -> rows r0+lane, koff 0; lanes 16-31 -> rows, koff 8
    const int a_row  = warp_m * 32 + (lane & 15);
    const int a_koff = (lane >> 4) << 3;
    const uint32_t sa_hi = smb + SM_AHI + ((uint32_t)a_row * LDA + a_koff) * 2;
    const uint32_t sa_lo = smb + SM_ALO + ((uint32_t)a_row * LDA + a_koff) * 2;
    // B ldmatrix.x4 (2 ntiles): lanes: n_local = (lane&7) + ((lane>>4)<<3); koff = ((lane>>3)&1)*8
    const int b_n    = warp_n * 64 + (lane & 7) + ((lane >> 4) << 3);
    const int b_koff = ((lane >> 3) & 1) << 3;
    const uint32_t sb_hi = smb + SM_BHI + ((uint32_t)b_n * LDA + b_koff) * 2;
    const uint32_t sb_lo = smb + SM_BLO + ((uint32_t)b_n * LDA + b_koff) * 2;

    float acc[2][8][4];
    #pragma unroll
    for (int mt = 0; mt < 2; mt++)
        #pragma unroll
        for (int nt = 0; nt < 8; nt++)
            #pragma unroll
            for (int r = 0; r < 4; r++) acc[mt][nt][r] = 0.f;

    #pragma unroll 2
    for (int kt = 0; kt < 8; kt++) {
        const uint32_t kb = kt * 32;              // 16 bf16 = 32 bytes
        uint32_t ah[2][4], al[2][4];
        ldsm_x4(ah[0], sa_hi + kb);
        ldsm_x4(ah[1], sa_hi + 16 * LDA * 2 + kb);
        ldsm_x4(al[0], sa_lo + kb);
        ldsm_x4(al[1], sa_lo + 16 * LDA * 2 + kb);
        uint32_t bh[4][4], bl[4][4];
        #pragma unroll
        for (int p = 0; p < 4; p++) {
            ldsm_x4(bh[p], sb_hi + (uint32_t)p * 16 * LDA * 2 + kb);
            ldsm_x4(bl[p], sb_lo + (uint32_t)p * 16 * LDA * 2 + kb);
        }
        #pragma unroll
        for (int mt = 0; mt < 2; mt++)
            #pragma unroll
            for (int p = 0; p < 4; p++)
                #pragma unroll
                for (int hf = 0; hf < 2; hf++) {
                    int nt = p * 2 + hf;
                    mma_bf16(acc[mt][nt], ah[mt], bh[p][hf*2], bh[p][hf*2+1]);
                    mma_bf16(acc[mt][nt], ah[mt], bl[p][hf*2], bl[p][hf*2+1]);
                    mma_bf16(acc[mt][nt], al[mt], bh[p][hf*2], bh[p][hf*2+1]);
                }
    }

    // ---- epilogue ----
    const float* sbias = (const float*)(sm + SM_BIAS);
    #pragma unroll
    for (int mt = 0; mt < 2; mt++) {
        int r0 = m0 + warp_m * 32 + mt * 16 + (lane >> 2);
        #pragma unroll
        for (int nt = 0; nt < 8; nt++) {
            int col = warp_n * 64 + nt * 8 + ((lane & 3) << 1);
            float v[4];
            #pragma unroll
            for (int r = 0; r < 4; r++) {
                float x = acc[mt][nt][r];
                if (BIAS) x += sbias[col + (r & 1)];
                if (SILU) x = x / (1.0f + expf(-x));
                v[r] = x;
            }
            if (r0 < M)     *(float2*)&C[(size_t)r0 * NF + col]       = make_float2(v[0], v[1]);
            if (r0 + 8 < M) *(float2*)&C[(size_t)(r0 + 8) * NF + col] = make_float2(v[2], v[3]);
        }
    }
}

// ---------------- init: atom = node_emb[z] ----------------
__global__ void init_atom_k(const int* __restrict__ z, const float* __restrict__ emb,
                            float* __restrict__ atom)
{
    int idx = blockIdx.x * blockDim.x + threadIdx.x;
    int n = idx >> 7, f = idx & 127;
    atom[idx] = emb[(size_t)z[n] * NF + f];
}

// ---------------- edge embedding ----------------
__global__ void edge_embed_k(const float* __restrict__ pos, const int* __restrict__ ei,
                             float* __restrict__ dist, float* __restrict__ dir)
{
    int e = blockIdx.x * blockDim.x + threadIdx.x;
    if (e >= N_EDGES) return;
    int i = ei[e], j = ei[N_EDGES + e];
    float dx = pos[j*3+0] - pos[i*3+0];
    float dy = pos[j*3+1] - pos[i*3+1];
    float dz = pos[j*3+2] - pos[i*3+2];
    float d = sqrtf(dx*dx + dy*dy + dz*dz + 1e-12f);
    float inv = 1.0f / d;
    dir[e*3+0] = dx*inv; dir[e*3+1] = dy*inv; dir[e*3+2] = dz*inv;
    float fc = (d < CUTOFF_R) ? 0.5f * (cosf(3.14159265358979323846f * d / CUTOFF_R) + 1.0f) : 0.0f;
    const float inv_w = 1.0f / (CUTOFF_R / NB);
    #pragma unroll
    for (int b = 0; b < NB; b++) {
        float c = CUTOFF_R * (float)b / (float)(NB - 1);
        float t = (d - c) * inv_w;
        dist[(size_t)e*NB + b] = expf(-t*t) * fc;
    }
}

// ---------------- msg = (dist @ me_W) * h[i] * h[j]; atom += segsum(msg, i) ----------------
__global__ void msg_k(const float* __restrict__ h, const float* __restrict__ dist,
                      const int* __restrict__ ei, const float* __restrict__ meW,
                      float* __restrict__ msg, float* __restrict__ atom)
{
    __shared__ float sW[NB * NF];
    __shared__ float sd[32 * NB];
    int f = threadIdx.x;
    #pragma unroll
    for (int b = 0; b < NB; b++) sW[b*NF + f] = meW[b*NF + f];
    int e0 = blockIdx.x * 32;
    for (int q = f; q < 32 * NB; q += NF) sd[q] = dist[(size_t)e0 * NB + q];
    __syncthreads();
    #pragma unroll 2
    for (int t = 0; t < 32; t++) {
        int e = e0 + t;
        int i = ei[e], j = ei[N_EDGES + e];
        float me = 0.f;
        #pragma unroll
        for (int b = 0; b < NB; b++) me = fmaf(sd[t*NB + b], sW[b*NF + f], me);
        float m = me * h[(size_t)i*NF + f] * h[(size_t)j*NF + f];
        msg[(size_t)e*NF + f] = m;
        atomicAdd(&atom[(size_t)i*NF + f], m);
    }
}

// ---------------- fdelta += segsum(p1*dir + p2*force[j], i) ----------------
__global__ void scatter_force_k(const float* __restrict__ p1, const float* __restrict__ p2,
                                const float* __restrict__ dir, const float* __restrict__ force,
                                const int* __restrict__ ei, float* __restrict__ fdelta)
{
    int f = threadIdx.x;
    int e0 = blockIdx.x * 8;
    for (int t = 0; t < 8; t++) {
        int e = e0 + t;
        int i = ei[e], j = ei[N_EDGES + e];
        float v1 = p1[(size_t)e*NF + f];
        float v2 = p2[(size_t)e*NF + f];
        float dx = dir[e*3+0], dy = dir[e*3+1], dz = dir[e*3+2];
        const float* fj = &force[(size_t)j * 3 * NF];
        float* fd = &fdelta[(size_t)i * 3 * NF];
        atomicAdd(&fd[0*NF + f], fmaf(v1, dx, v2 * fj[0*NF + f]));
        atomicAdd(&fd[1*NF + f], fmaf(v1, dy, v2 * fj[1*NF + f]));
        atomicAdd(&fd[2*NF + f], fmaf(v1, dz, v2 * fj[2*NF + f]));
    }
}

// ---------------- force += fdelta; fdelta = 0 ----------------
__global__ void force_update_k(float* __restrict__ force, float* __restrict__ fdelta)
{
    int idx = blockIdx.x * blockDim.x + threadIdx.x;
    force[idx] += fdelta[idx];
    fdelta[idx] = 0.f;
}

// ---------------- atom += sum_d force[n,d,:] * g[n,d,:] ----------------
__global__ void atom_update_k(float* __restrict__ atom, const float* __restrict__ force,
                              const float* __restrict__ g)
{
    int idx = blockIdx.x * blockDim.x + threadIdx.x;
    int n = idx >> 7, f = idx & 127;
    size_t base = (size_t)n * 3 * NF + f;
    float s = force[base]        * g[base]
            + force[base + NF]   * g[base + NF]
            + force[base + 2*NF] * g[base + 2*NF];
    atom[idx] += s;
}

// ---------------- host ----------------
extern "C" void kernel_launch(void* const* d_in, const int* in_sizes, int n_in,
                              void* d_out, int out_size)
{
    const int*   z        = (const int*)  d_in[0];
    const float* pos      = (const float*)d_in[1];
    const int*   ei       = (const int*)  d_in[4];
    const float* node_emb = (const float*)d_in[5];
    const float* mnp_W1   = (const float*)d_in[6];
    const float* mnp_b1   = (const float*)d_in[7];
    const float* mnp_W2   = (const float*)d_in[8];
    const float* mnp_b2   = (const float*)d_in[9];
    const float* me_W     = (const float*)d_in[10];
    const float* em1_W1   = (const float*)d_in[11];
    const float* em1_W2   = (const float*)d_in[12];
    const float* em2_W1   = (const float*)d_in[13];
    const float* em2_W2   = (const float*)d_in[14];
    const float* eu_W     = (const float*)d_in[15];

    float* atom  = (float*)d_out;
    float* force;

    float *dist, *dir, *h, *msg, *abuf, *p1, *p2, *fdelta, *force_fb;
    cudaGetSymbolAddress((void**)&dist,     g_dist);
    cudaGetSymbolAddress((void**)&dir,      g_dir);
    cudaGetSymbolAddress((void**)&h,        g_h);
    cudaGetSymbolAddress((void**)&msg,      g_msg);
    cudaGetSymbolAddress((void**)&abuf,     g_a);
    cudaGetSymbolAddress((void**)&p1,       g_p1);
    cudaGetSymbolAddress((void**)&p2,       g_p2);
    cudaGetSymbolAddress((void**)&fdelta,   g_fdelta);
    cudaGetSymbolAddress((void**)&force_fb, g_force_fb);

    if (out_size >= N_NODES * (NF + 3 * NF)) force = atom + (size_t)N_NODES * NF;
    else                                     force = force_fb;

    cudaFuncSetAttribute(mma_gemm_k<true,  true >, cudaFuncAttributeMaxDynamicSharedMemorySize, SM_TOTAL);
    cudaFuncSetAttribute(mma_gemm_k<false, true >, cudaFuncAttributeMaxDynamicSharedMemorySize, SM_TOTAL);
    cudaFuncSetAttribute(mma_gemm_k<true,  false>, cudaFuncAttributeMaxDynamicSharedMemorySize, SM_TOTAL);
    cudaFuncSetAttribute(mma_gemm_k<false, false>, cudaFuncAttributeMaxDynamicSharedMemorySize, SM_TOTAL);

    cudaMemsetAsync(force,  0, (size_t)N_NODES * 3 * NF * sizeof(float), 0);
    cudaMemsetAsync(fdelta, 0, (size_t)N_NODES * 3 * NF * sizeof(float), 0);

    init_atom_k<<<(N_NODES * NF) / 256, 256>>>(z, node_emb, atom);
    edge_embed_k<<<(N_EDGES + 255) / 256, 256>>>(pos, ei, dist, dir);

    const int GN  = (N_NODES + 127) / 128;       // 79
    const int GE  = N_EDGES / 128;               // 1250
    const int GF3 = (N_NODES * 3 + 127) / 128;   // 235

    for (int l = 0; l < NLAYERS; l++) {
        const float* W1 = mnp_W1 + (size_t)l * NF * NF;
        const float* b1 = mnp_b1 + (size_t)l * NF;
        const float* W2 = mnp_W2 + (size_t)l * NF * NF;
        const float* b2 = mnp_b2 + (size_t)l * NF;
        const float* mW = me_W   + (size_t)l * NB * NF;
        const float* e11 = em1_W1 + (size_t)l * NF * NF;
        const float* e12 = em1_W2 + (size_t)l * NF * NF;
        const float* e21 = em2_W1 + (size_t)l * NF * NF;
        const float* e22 = em2_W2 + (size_t)l * NF * NF;
        const float* euW = eu_W   + (size_t)l * NF * NF;

        // h = silu(atom @ W1 + b1) @ W2 + b2
        mma_gemm_k<true,  true ><<<GN, 256, SM_TOTAL>>>(atom, W1, b1, abuf, N_NODES);
        mma_gemm_k<false, true ><<<GN, 256, SM_TOTAL>>>(abuf, W2, b2, h,    N_NODES);

        // msg + atom segsum
        msg_k<<<N_EDGES / 32, NF>>>(h, dist, ei, mW, msg, atom);

        // p1 = silu(msg@e11)@e12 ; p2 = silu(msg@e21)@e22
        mma_gemm_k<true,  false><<<GE, 256, SM_TOTAL>>>(msg,  e11, nullptr, abuf, N_EDGES);
        mma_gemm_k<false, false><<<GE, 256, SM_TOTAL>>>(abuf, e12, nullptr, p1,   N_EDGES);
        mma_gemm_k<true,  false><<<GE, 256, SM_TOTAL>>>(msg,  e21, nullptr, abuf, N_EDGES);
        mma_gemm_k<false, false><<<GE, 256, SM_TOTAL>>>(abuf, e22, nullptr, p2,   N_EDGES);

        // force delta scatter, then force update (+ fdelta re-zero)
        scatter_force_k<<<N_EDGES / 8, NF>>>(p1, p2, dir, force, ei, fdelta);
        force_update_k<<<(N_NODES * 3 * NF) / 256, 256>>>(force, fdelta);

        // g = force @ eu_W  (rows = N*3); reuse p1 as g
        mma_gemm_k<false, false><<<GF3, 256, SM_TOTAL>>>(force, euW, nullptr, p1, N_NODES * 3);
        atom_update_k<<<(N_NODES * NF) / 256, 256>>>(atom, force, p1);
    }
}

// round 6
// speedup vs baseline: 1.5599x; 1.4332x over previous
#include <cuda_runtime.h>
#include <cuda_bf16.h>
#include <math.h>
#include <stdint.h>

#define N_NODES 10000
#define N_EDGES 160000
#define NF 128
#define NB 20
#define NLAYERS 3
#define CUTOFF_R 5.0f

typedef __nv_bfloat16 bf16;

// ---------------- device scratch ----------------
__device__ float g_dist[(size_t)N_EDGES * NB];
__device__ float g_dir[(size_t)N_EDGES * 3];
__device__ float g_h[(size_t)N_NODES * NF];
__device__ float g_p1[(size_t)N_EDGES * NF];
__device__ float g_p2[(size_t)N_EDGES * NF];
__device__ float g_fdelta[(size_t)N_NODES * 3 * NF];
__device__ float g_force_fb[(size_t)N_NODES * 3 * NF];
// bf16 hi/lo activation buffers
__device__ bf16 g_bhi1[(size_t)N_EDGES * NF];   // atom -> msg
__device__ bf16 g_blo1[(size_t)N_EDGES * NF];
__device__ bf16 g_bhi2[(size_t)N_EDGES * NF];   // silu intermediates / force
__device__ bf16 g_blo2[(size_t)N_EDGES * NF];
// pre-transposed split weights: 21 matrices of 128x128 (Bt[n][k])
__device__ bf16 g_whi[21 * 16384];
__device__ bf16 g_wlo[21 * 16384];

// ============================ helpers ============================
__device__ __forceinline__ uint32_t smem_u32(const void* p) {
    uint32_t a;
    asm("{ .reg .u64 t; cvta.to.shared.u64 t, %1; cvt.u32.u64 %0, t; }" : "=r"(a) : "l"(p));
    return a;
}
__device__ __forceinline__ void ldsm_x4(uint32_t* r, uint32_t addr) {
    asm volatile("ldmatrix.sync.aligned.m8n8.x4.shared.b16 {%0,%1,%2,%3}, [%4];"
                 : "=r"(r[0]), "=r"(r[1]), "=r"(r[2]), "=r"(r[3]) : "r"(addr));
}
__device__ __forceinline__ void mma_bf16(float* d, const uint32_t* a, uint32_t b0, uint32_t b1) {
    asm volatile(
        "mma.sync.aligned.m16n8k16.row.col.f32.bf16.bf16.f32 "
        "{%0,%1,%2,%3},{%4,%5,%6,%7},{%8,%9},{%0,%1,%2,%3};"
        : "+f"(d[0]), "+f"(d[1]), "+f"(d[2]), "+f"(d[3])
        : "r"(a[0]), "r"(a[1]), "r"(a[2]), "r"(a[3]), "r"(b0), "r"(b1));
}
__device__ __forceinline__ void split_bf16(float v, bf16& h, bf16& l) {
    h = __float2bfloat16(v);
    l = __float2bfloat16(v - __bfloat162float(h));
}

// ---------------- weight prep: transpose + split, one matrix per block ----------------
// src: [nmat][128][128] fp32 (stride 16384); dst: base already offset; per-block dst stride = 7*16384
#define PREP_SM (2 * 128 * 136 * 2)   // 69632
__global__ void prep_w_k(const float* __restrict__ src,
                         bf16* __restrict__ dhi, bf16* __restrict__ dlo)
{
    extern __shared__ char sm[];
    bf16* shi = (bf16*)sm;                  // [128][136]
    bf16* slo = (bf16*)(sm + 128 * 136 * 2);
    const int tid = threadIdx.x;
    const float4* s4 = reinterpret_cast<const float4*>(src + (size_t)blockIdx.x * 16384);
    #pragma unroll 4
    for (int q = 0; q < 16; q++) {
        int lin = q * 256 + tid;            // 4096 float4
        int k = lin >> 5, n4 = (lin & 31) << 2;
        float4 v = s4[lin];
        float vv[4] = {v.x, v.y, v.z, v.w};
        #pragma unroll
        for (int t = 0; t < 4; t++) {
            bf16 hb, lb; split_bf16(vv[t], hb, lb);
            shi[(n4 + t) * 136 + k] = hb;
            slo[(n4 + t) * 136 + k] = lb;
        }
    }
    __syncthreads();
    uint4* dh4 = reinterpret_cast<uint4*>(dhi + (size_t)blockIdx.x * 7 * 16384);
    uint4* dl4 = reinterpret_cast<uint4*>(dlo + (size_t)blockIdx.x * 7 * 16384);
    const char* smc = sm;
    #pragma unroll 4
    for (int q = 0; q < 8; q++) {
        int lin = q * 256 + tid;            // 2048 uint4
        int row = lin >> 4, seg = lin & 15;
        dh4[lin] = *(const uint4*)(smc + row * 272 + seg * 16);
        dl4[lin] = *(const uint4*)(smc + 128 * 136 * 2 + row * 272 + seg * 16);
    }
}

// ---------------- fp32 -> bf16 hi/lo convert ----------------
__global__ void conv_k(const float* __restrict__ x, bf16* __restrict__ hi,
                       bf16* __restrict__ lo, int n4)
{
    int i = blockIdx.x * blockDim.x + threadIdx.x;
    if (i >= n4) return;
    float4 v = reinterpret_cast<const float4*>(x)[i];
    float vv[4] = {v.x, v.y, v.z, v.w};
    uint16_t h[4], l[4];
    #pragma unroll
    for (int t = 0; t < 4; t++) {
        bf16 hb, lb; split_bf16(vv[t], hb, lb);
        h[t] = __bfloat16_as_ushort(hb); l[t] = __bfloat16_as_ushort(lb);
    }
    reinterpret_cast<uint2*>(hi)[i] = make_uint2((uint32_t)h[0] | ((uint32_t)h[1] << 16),
                                                 (uint32_t)h[2] | ((uint32_t)h[3] << 16));
    reinterpret_cast<uint2*>(lo)[i] = make_uint2((uint32_t)l[0] | ((uint32_t)l[1] << 16),
                                                 (uint32_t)l[2] | ((uint32_t)l[3] << 16));
}

// ============================ HMMA GEMM v2 ============================
// C[M,128] = A[M,128] @ Bt^T, A and Bt pre-split bf16 hi/lo.
// 256 thr, tile 128x128, warp = 32 rows x 64 cols.
#define LDA 136
#define A_BYTES (128 * LDA * 2)
#define SM_AHI  0
#define SM_ALO  (A_BYTES)
#define SM_BHI  (2 * A_BYTES)
#define SM_BLO  (3 * A_BYTES)
#define SM_BIAS (4 * A_BYTES)
#define SM_TOTAL (4 * A_BYTES + 512)

template<bool SILU, bool BIAS, bool OUTBF>
__global__ void __launch_bounds__(256) mma_gemm2_k(
    const bf16* __restrict__ Ahi, const bf16* __restrict__ Alo,
    const bf16* __restrict__ Bhi, const bf16* __restrict__ Blo,
    const float* __restrict__ bias, float* __restrict__ Cf,
    bf16* __restrict__ Chi, bf16* __restrict__ Clo, int M)
{
    extern __shared__ char sm[];
    const uint32_t smb = smem_u32(sm);
    const int tid  = threadIdx.x;
    const int wid  = tid >> 5;
    const int lane = tid & 31;
    const int m0   = blockIdx.x * 128;
    const int warp_m = wid >> 1;
    const int warp_n = wid & 1;

    if (BIAS && tid < 128) ((float*)(sm + SM_BIAS))[tid] = bias[tid];

    // B tiles (always full 128 rows)
    {
        const uint4* bh4 = reinterpret_cast<const uint4*>(Bhi);
        const uint4* bl4 = reinterpret_cast<const uint4*>(Blo);
        #pragma unroll 4
        for (int q = 0; q < 8; q++) {
            int lin = q * 256 + tid;        // 2048
            int row = lin >> 4, seg = lin & 15;
            *(uint4*)(sm + SM_BHI + row * 272 + seg * 16) = bh4[lin];
            *(uint4*)(sm + SM_BLO + row * 272 + seg * 16) = bl4[lin];
        }
    }
    // A tiles (bound-checked)
    {
        const uint4* ah4 = reinterpret_cast<const uint4*>(Ahi);
        const uint4* al4 = reinterpret_cast<const uint4*>(Alo);
        #pragma unroll 4
        for (int q = 0; q < 8; q++) {
            int lin = q * 256 + tid;        // 2048
            int row = lin >> 4, seg = lin & 15;
            uint4 vh = make_uint4(0u,0u,0u,0u), vl = make_uint4(0u,0u,0u,0u);
            if (m0 + row < M) {
                size_t gi = (size_t)(m0 + row) * 16 + seg;
                vh = ah4[gi]; vl = al4[gi];
            }
            *(uint4*)(sm + SM_AHI + row * 272 + seg * 16) = vh;
            *(uint4*)(sm + SM_ALO + row * 272 + seg * 16) = vl;
        }
    }
    __syncthreads();

    const int a_row  = warp_m * 32 + (lane & 15);
    const int a_koff = (lane >> 4) << 3;
    const uint32_t sa_hi = smb + SM_AHI + ((uint32_t)a_row * LDA + a_koff) * 2;
    const uint32_t sa_lo = smb + SM_ALO + ((uint32_t)a_row * LDA + a_koff) * 2;
    const int b_n    = warp_n * 64 + (lane & 7) + ((lane >> 4) << 3);
    const int b_koff = ((lane >> 3) & 1) << 3;
    const uint32_t sb_hi = smb + SM_BHI + ((uint32_t)b_n * LDA + b_koff) * 2;
    const uint32_t sb_lo = smb + SM_BLO + ((uint32_t)b_n * LDA + b_koff) * 2;

    float acc[2][8][4];
    #pragma unroll
    for (int mt = 0; mt < 2; mt++)
        #pragma unroll
        for (int nt = 0; nt < 8; nt++)
            #pragma unroll
            for (int r = 0; r < 4; r++) acc[mt][nt][r] = 0.f;

    #pragma unroll 2
    for (int kt = 0; kt < 8; kt++) {
        const uint32_t kb = kt * 32;
        uint32_t ah[2][4], al[2][4];
        ldsm_x4(ah[0], sa_hi + kb);
        ldsm_x4(ah[1], sa_hi + 16 * LDA * 2 + kb);
        ldsm_x4(al[0], sa_lo + kb);
        ldsm_x4(al[1], sa_lo + 16 * LDA * 2 + kb);
        uint32_t bh[4][4], bl[4][4];
        #pragma unroll
        for (int p = 0; p < 4; p++) {
            ldsm_x4(bh[p], sb_hi + (uint32_t)p * 16 * LDA * 2 + kb);
            ldsm_x4(bl[p], sb_lo + (uint32_t)p * 16 * LDA * 2 + kb);
        }
        #pragma unroll
        for (int mt = 0; mt < 2; mt++)
            #pragma unroll
            for (int p = 0; p < 4; p++)
                #pragma unroll
                for (int hf = 0; hf < 2; hf++) {
                    int nt = p * 2 + hf;
                    mma_bf16(acc[mt][nt], ah[mt], bh[p][hf*2], bh[p][hf*2+1]);
                    mma_bf16(acc[mt][nt], ah[mt], bl[p][hf*2], bl[p][hf*2+1]);
                    mma_bf16(acc[mt][nt], al[mt], bh[p][hf*2], bh[p][hf*2+1]);
                }
    }

    const float* sbias = (const float*)(sm + SM_BIAS);
    #pragma unroll
    for (int mt = 0; mt < 2; mt++) {
        int r0 = m0 + warp_m * 32 + mt * 16 + (lane >> 2);
        #pragma unroll
        for (int nt = 0; nt < 8; nt++) {
            int col = warp_n * 64 + nt * 8 + ((lane & 3) << 1);
            float v[4];
            #pragma unroll
            for (int r = 0; r < 4; r++) {
                float x = acc[mt][nt][r];
                if (BIAS) x += sbias[col + (r & 1)];
                if (SILU) x = x / (1.0f + expf(-x));
                v[r] = x;
            }
            if (OUTBF) {
                #pragma unroll
                for (int half = 0; half < 2; half++) {
                    int rr = r0 + half * 8;
                    if (rr < M) {
                        bf16 h0, l0, h1, l1;
                        split_bf16(v[half*2+0], h0, l0);
                        split_bf16(v[half*2+1], h1, l1);
                        size_t ix = (size_t)rr * NF + col;
                        *(uint32_t*)&Chi[ix] = (uint32_t)__bfloat16_as_ushort(h0)
                                             | ((uint32_t)__bfloat16_as_ushort(h1) << 16);
                        *(uint32_t*)&Clo[ix] = (uint32_t)__bfloat16_as_ushort(l0)
                                             | ((uint32_t)__bfloat16_as_ushort(l1) << 16);
                    }
                }
            } else {
                if (r0 < M)     *(float2*)&Cf[(size_t)r0 * NF + col]       = make_float2(v[0], v[1]);
                if (r0 + 8 < M) *(float2*)&Cf[(size_t)(r0 + 8) * NF + col] = make_float2(v[2], v[3]);
            }
        }
    }
}

// ---------------- init: atom = node_emb[z] ----------------
__global__ void init_atom_k(const int* __restrict__ z, const float* __restrict__ emb,
                            float* __restrict__ atom)
{
    int idx = blockIdx.x * blockDim.x + threadIdx.x;
    int n = idx >> 7, f = idx & 127;
    atom[idx] = emb[(size_t)z[n] * NF + f];
}

// ---------------- edge embedding ----------------
__global__ void edge_embed_k(const float* __restrict__ pos, const int* __restrict__ ei,
                             float* __restrict__ dist, float* __restrict__ dir)
{
    int e = blockIdx.x * blockDim.x + threadIdx.x;
    if (e >= N_EDGES) return;
    int i = ei[e], j = ei[N_EDGES + e];
    float dx = pos[j*3+0] - pos[i*3+0];
    float dy = pos[j*3+1] - pos[i*3+1];
    float dz = pos[j*3+2] - pos[i*3+2];
    float d = sqrtf(dx*dx + dy*dy + dz*dz + 1e-12f);
    float inv = 1.0f / d;
    dir[e*3+0] = dx*inv; dir[e*3+1] = dy*inv; dir[e*3+2] = dz*inv;
    float fc = (d < CUTOFF_R) ? 0.5f * (cosf(3.14159265358979323846f * d / CUTOFF_R) + 1.0f) : 0.0f;
    const float inv_w = 1.0f / (CUTOFF_R / NB);
    #pragma unroll
    for (int b = 0; b < NB; b++) {
        float c = CUTOFF_R * (float)b / (float)(NB - 1);
        float t = (d - c) * inv_w;
        dist[(size_t)e*NB + b] = expf(-t*t) * fc;
    }
}

// ---------------- msg: hi/lo out + atom segsum ----------------
__global__ void msg_k2(const float* __restrict__ h, const float* __restrict__ dist,
                       const int* __restrict__ ei, const float* __restrict__ meW,
                       bf16* __restrict__ mhi, bf16* __restrict__ mlo,
                       float* __restrict__ atom)
{
    __shared__ float sW[NB * NF];
    __shared__ float sd[32 * NB];
    int f = threadIdx.x;
    #pragma unroll
    for (int b = 0; b < NB; b++) sW[b*NF + f] = meW[b*NF + f];
    int e0 = blockIdx.x * 32;
    for (int q = f; q < 32 * NB; q += NF) sd[q] = dist[(size_t)e0 * NB + q];
    __syncthreads();
    #pragma unroll 2
    for (int t = 0; t < 32; t++) {
        int e = e0 + t;
        int i = ei[e], j = ei[N_EDGES + e];
        float me = 0.f;
        #pragma unroll
        for (int b = 0; b < NB; b++) me = fmaf(sd[t*NB + b], sW[b*NF + f], me);
        float m = me * h[(size_t)i*NF + f] * h[(size_t)j*NF + f];
        bf16 hb, lb; split_bf16(m, hb, lb);
        mhi[(size_t)e*NF + f] = hb;
        mlo[(size_t)e*NF + f] = lb;
        atomicAdd(&atom[(size_t)i*NF + f], m);
    }
}

// ---------------- fdelta += segsum(p1*dir + p2*force[j], i) ----------------
__global__ void scatter_force_k(const float* __restrict__ p1, const float* __restrict__ p2,
                                const float* __restrict__ dir, const float* __restrict__ force,
                                const int* __restrict__ ei, float* __restrict__ fdelta)
{
    int f = threadIdx.x;
    int e0 = blockIdx.x * 8;
    for (int t = 0; t < 8; t++) {
        int e = e0 + t;
        int i = ei[e], j = ei[N_EDGES + e];
        float v1 = p1[(size_t)e*NF + f];
        float v2 = p2[(size_t)e*NF + f];
        float dx = dir[e*3+0], dy = dir[e*3+1], dz = dir[e*3+2];
        const float* fj = &force[(size_t)j * 3 * NF];
        float* fd = &fdelta[(size_t)i * 3 * NF];
        atomicAdd(&fd[0*NF + f], fmaf(v1, dx, v2 * fj[0*NF + f]));
        atomicAdd(&fd[1*NF + f], fmaf(v1, dy, v2 * fj[1*NF + f]));
        atomicAdd(&fd[2*NF + f], fmaf(v1, dz, v2 * fj[2*NF + f]));
    }
}

// ---------------- force += fdelta; fdelta=0; emit hi/lo ----------------
__global__ void force_update_k2(float* __restrict__ force, float* __restrict__ fdelta,
                                bf16* __restrict__ fhi, bf16* __restrict__ flo)
{
    int idx = blockIdx.x * blockDim.x + threadIdx.x;
    float v = force[idx] + fdelta[idx];
    force[idx] = v;
    fdelta[idx] = 0.f;
    bf16 hb, lb; split_bf16(v, hb, lb);
    fhi[idx] = hb; flo[idx] = lb;
}

// ---------------- atom += sum_d force[n,d,:] * g[n,d,:] ----------------
__global__ void atom_update_k(float* __restrict__ atom, const float* __restrict__ force,
                              const float* __restrict__ g)
{
    int idx = blockIdx.x * blockDim.x + threadIdx.x;
    int n = idx >> 7, f = idx & 127;
    size_t base = (size_t)n * 3 * NF + f;
    float s = force[base]        * g[base]
            + force[base + NF]   * g[base + NF]
            + force[base + 2*NF] * g[base + 2*NF];
    atom[idx] += s;
}

// ---------------- host ----------------
extern "C" void kernel_launch(void* const* d_in, const int* in_sizes, int n_in,
                              void* d_out, int out_size)
{
    const int*   z        = (const int*)  d_in[0];
    const float* pos      = (const float*)d_in[1];
    const int*   ei       = (const int*)  d_in[4];
    const float* node_emb = (const float*)d_in[5];
    const float* mnp_W1   = (const float*)d_in[6];
    const float* mnp_b1   = (const float*)d_in[7];
    const float* mnp_W2   = (const float*)d_in[8];
    const float* mnp_b2   = (const float*)d_in[9];
    const float* me_W     = (const float*)d_in[10];
    const float* em1_W1   = (const float*)d_in[11];
    const float* em1_W2   = (const float*)d_in[12];
    const float* em2_W1   = (const float*)d_in[13];
    const float* em2_W2   = (const float*)d_in[14];
    const float* eu_W     = (const float*)d_in[15];

    float* atom = (float*)d_out;
    float* force;

    float *dist, *dir, *h, *p1, *p2, *fdelta, *force_fb;
    bf16 *bhi1, *blo1, *bhi2, *blo2, *whi, *wlo;
    cudaGetSymbolAddress((void**)&dist,     g_dist);
    cudaGetSymbolAddress((void**)&dir,      g_dir);
    cudaGetSymbolAddress((void**)&h,        g_h);
    cudaGetSymbolAddress((void**)&p1,       g_p1);
    cudaGetSymbolAddress((void**)&p2,       g_p2);
    cudaGetSymbolAddress((void**)&fdelta,   g_fdelta);
    cudaGetSymbolAddress((void**)&force_fb, g_force_fb);
    cudaGetSymbolAddress((void**)&bhi1, g_bhi1);
    cudaGetSymbolAddress((void**)&blo1, g_blo1);
    cudaGetSymbolAddress((void**)&bhi2, g_bhi2);
    cudaGetSymbolAddress((void**)&blo2, g_blo2);
    cudaGetSymbolAddress((void**)&whi,  g_whi);
    cudaGetSymbolAddress((void**)&wlo,  g_wlo);

    if (out_size >= N_NODES * (NF + 3 * NF)) force = atom + (size_t)N_NODES * NF;
    else                                     force = force_fb;

    cudaFuncSetAttribute(mma_gemm2_k<true,  true,  true >, cudaFuncAttributeMaxDynamicSharedMemorySize, SM_TOTAL);
    cudaFuncSetAttribute(mma_gemm2_k<false, true,  false>, cudaFuncAttributeMaxDynamicSharedMemorySize, SM_TOTAL);
    cudaFuncSetAttribute(mma_gemm2_k<true,  false, true >, cudaFuncAttributeMaxDynamicSharedMemorySize, SM_TOTAL);
    cudaFuncSetAttribute(mma_gemm2_k<false, false, false>, cudaFuncAttributeMaxDynamicSharedMemorySize, SM_TOTAL);
    cudaFuncSetAttribute(prep_w_k, cudaFuncAttributeMaxDynamicSharedMemorySize, PREP_SM);

    // weight prep: 7 families x 3 layers -> slots (l*7 + which)
    prep_w_k<<<3, 256, PREP_SM>>>(mnp_W1, whi + 0*16384, wlo + 0*16384);
    prep_w_k<<<3, 256, PREP_SM>>>(mnp_W2, whi + 1*16384, wlo + 1*16384);
    prep_w_k<<<3, 256, PREP_SM>>>(em1_W1, whi + 2*16384, wlo + 2*16384);
    prep_w_k<<<3, 256, PREP_SM>>>(em1_W2, whi + 3*16384, wlo + 3*16384);
    prep_w_k<<<3, 256, PREP_SM>>>(em2_W1, whi + 4*16384, wlo + 4*16384);
    prep_w_k<<<3, 256, PREP_SM>>>(em2_W2, whi + 5*16384, wlo + 5*16384);
    prep_w_k<<<3, 256, PREP_SM>>>(eu_W,   whi + 6*16384, wlo + 6*16384);

    cudaMemsetAsync(force,  0, (size_t)N_NODES * 3 * NF * sizeof(float), 0);
    cudaMemsetAsync(fdelta, 0, (size_t)N_NODES * 3 * NF * sizeof(float), 0);

    init_atom_k<<<(N_NODES * NF) / 256, 256>>>(z, node_emb, atom);
    edge_embed_k<<<(N_EDGES + 255) / 256, 256>>>(pos, ei, dist, dir);

    const int GN  = (N_NODES + 127) / 128;       // 79
    const int GE  = N_EDGES / 128;               // 1250
    const int GF3 = (N_NODES * 3 + 127) / 128;   // 235

    for (int l = 0; l < NLAYERS; l++) {
        const bf16* Whi = whi + (size_t)l * 7 * 16384;
        const bf16* Wlo = wlo + (size_t)l * 7 * 16384;
        const float* b1 = mnp_b1 + (size_t)l * NF;
        const float* b2 = mnp_b2 + (size_t)l * NF;
        const float* mW = me_W   + (size_t)l * NB * NF;

        // atom -> hi/lo
        conv_k<<<(N_NODES * NF / 4 + 255) / 256, 256>>>(atom, bhi1, blo1, N_NODES * NF / 4);

        // h = silu(atom@W1+b1)@W2+b2
        mma_gemm2_k<true,  true,  true ><<<GN, 256, SM_TOTAL>>>(bhi1, blo1, Whi + 0*16384, Wlo + 0*16384, b1, nullptr, bhi2, blo2, N_NODES);
        mma_gemm2_k<false, true,  false><<<GN, 256, SM_TOTAL>>>(bhi2, blo2, Whi + 1*16384, Wlo + 1*16384, b2, h, nullptr, nullptr, N_NODES);

        // msg (hi/lo) + atom segsum
        msg_k2<<<N_EDGES / 32, NF>>>(h, dist, ei, mW, bhi1, blo1, atom);

        // p1 = silu(msg@e11)@e12 ; p2 = silu(msg@e21)@e22
        mma_gemm2_k<true,  false, true ><<<GE, 256, SM_TOTAL>>>(bhi1, blo1, Whi + 2*16384, Wlo + 2*16384, nullptr, nullptr, bhi2, blo2, N_EDGES);
        mma_gemm2_k<false, false, false><<<GE, 256, SM_TOTAL>>>(bhi2, blo2, Whi + 3*16384, Wlo + 3*16384, nullptr, p1, nullptr, nullptr, N_EDGES);
        mma_gemm2_k<true,  false, true ><<<GE, 256, SM_TOTAL>>>(bhi1, blo1, Whi + 4*16384, Wlo + 4*16384, nullptr, nullptr, bhi2, blo2, N_EDGES);
        mma_gemm2_k<false, false, false><<<GE, 256, SM_TOTAL>>>(bhi2, blo2, Whi + 5*16384, Wlo + 5*16384, nullptr, p2, nullptr, nullptr, N_EDGES);

        // scatter + force update (emits force hi/lo into bhi2/blo2)
        scatter_force_k<<<N_EDGES / 8, NF>>>(p1, p2, dir, force, ei, fdelta);
        force_update_k2<<<(N_NODES * 3 * NF) / 256, 256>>>(force, fdelta, bhi2, blo2);

        // g = force @ eu_W -> p1 (fp32), then atom update
        mma_gemm2_k<false, false, false><<<GF3, 256, SM_TOTAL>>>(bhi2, blo2, Whi + 6*16384, Wlo + 6*16384, nullptr, p1, nullptr, nullptr, N_NODES * 3);
        atom_update_k<<<(N_NODES * NF) / 256, 256>>>(atom, force, p1);
    }
}

// round 9
// speedup vs baseline: 1.7517x; 1.1230x over previous
#include <cuda_runtime.h>
#include <cuda_bf16.h>
#include <math.h>
#include <stdint.h>

#define N_NODES 10000
#define N_EDGES 160000
#define NF 128
#define NB 20
#define NLAYERS 3
#define CUTOFF_R 5.0f

typedef __nv_bfloat16 bf16;

// ---------------- device scratch ----------------
__device__ float g_dist[(size_t)N_EDGES * NB];
__device__ float g_dir[(size_t)N_EDGES * 3];
__device__ float g_h[(size_t)N_NODES * NF];
__device__ float g_p1[(size_t)N_EDGES * NF];
__device__ float g_p2[(size_t)N_EDGES * NF];
__device__ float g_fdelta[(size_t)N_NODES * 3 * NF];
__device__ float g_force_fb[(size_t)N_NODES * 3 * NF];
__device__ bf16 g_bhi1[(size_t)N_EDGES * NF];   // atom / msg hi
__device__ bf16 g_blo1[(size_t)N_EDGES * NF];
__device__ bf16 g_bhi2[(size_t)N_NODES * 3 * NF];   // force hi
__device__ bf16 g_blo2[(size_t)N_NODES * 3 * NF];
__device__ bf16 g_whi[21 * 16384];
__device__ bf16 g_wlo[21 * 16384];

// ============================ helpers ============================
__device__ __forceinline__ uint32_t smem_u32(const void* p) {
    uint32_t a;
    asm("{ .reg .u64 t; cvta.to.shared.u64 t, %1; cvt.u32.u64 %0, t; }" : "=r"(a) : "l"(p));
    return a;
}
__device__ __forceinline__ void ldsm_x4(uint32_t* r, uint32_t addr) {
    asm volatile("ldmatrix.sync.aligned.m8n8.x4.shared.b16 {%0,%1,%2,%3}, [%4];"
                 : "=r"(r[0]), "=r"(r[1]), "=r"(r[2]), "=r"(r[3]) : "r"(addr));
}
__device__ __forceinline__ void mma_bf16(float* d, const uint32_t* a, uint32_t b0, uint32_t b1) {
    asm volatile(
        "mma.sync.aligned.m16n8k16.row.col.f32.bf16.bf16.f32 "
        "{%0,%1,%2,%3},{%4,%5,%6,%7},{%8,%9},{%0,%1,%2,%3};"
        : "+f"(d[0]), "+f"(d[1]), "+f"(d[2]), "+f"(d[3])
        : "r"(a[0]), "r"(a[1]), "r"(a[2]), "r"(a[3]), "r"(b0), "r"(b1));
}
__device__ __forceinline__ void split_bf16(float v, bf16& h, bf16& l) {
    h = __float2bfloat16(v);
    l = __float2bfloat16(v - __bfloat162float(h));
}

// ---------------- weight prep ----------------
#define PREP_SM (2 * 128 * 136 * 2)
__global__ void prep_w_k(const float* __restrict__ src,
                         bf16* __restrict__ dhi, bf16* __restrict__ dlo)
{
    extern __shared__ char sm[];
    bf16* shi = (bf16*)sm;
    bf16* slo = (bf16*)(sm + 128 * 136 * 2);
    const int tid = threadIdx.x;
    const float4* s4 = reinterpret_cast<const float4*>(src + (size_t)blockIdx.x * 16384);
    #pragma unroll 4
    for (int q = 0; q < 16; q++) {
        int lin = q * 256 + tid;
        int k = lin >> 5, n4 = (lin & 31) << 2;
        float4 v = s4[lin];
        float vv[4] = {v.x, v.y, v.z, v.w};
        #pragma unroll
        for (int t = 0; t < 4; t++) {
            bf16 hb, lb; split_bf16(vv[t], hb, lb);
            shi[(n4 + t) * 136 + k] = hb;
            slo[(n4 + t) * 136 + k] = lb;
        }
    }
    __syncthreads();
    uint4* dh4 = reinterpret_cast<uint4*>(dhi + (size_t)blockIdx.x * 7 * 16384);
    uint4* dl4 = reinterpret_cast<uint4*>(dlo + (size_t)blockIdx.x * 7 * 16384);
    const char* smc = sm;
    #pragma unroll 4
    for (int q = 0; q < 8; q++) {
        int lin = q * 256 + tid;
        int row = lin >> 4, seg = lin & 15;
        dh4[lin] = *(const uint4*)(smc + row * 272 + seg * 16);
        dl4[lin] = *(const uint4*)(smc + 128 * 136 * 2 + row * 272 + seg * 16);
    }
}

// ---------------- fp32 -> bf16 hi/lo ----------------
__global__ void conv_k(const float* __restrict__ x, bf16* __restrict__ hi,
                       bf16* __restrict__ lo, int n4)
{
    int i = blockIdx.x * blockDim.x + threadIdx.x;
    if (i >= n4) return;
    float4 v = reinterpret_cast<const float4*>(x)[i];
    float vv[4] = {v.x, v.y, v.z, v.w};
    uint16_t h[4], l[4];
    #pragma unroll
    for (int t = 0; t < 4; t++) {
        bf16 hb, lb; split_bf16(vv[t], hb, lb);
        h[t] = __bfloat16_as_ushort(hb); l[t] = __bfloat16_as_ushort(lb);
    }
    reinterpret_cast<uint2*>(hi)[i] = make_uint2((uint32_t)h[0] | ((uint32_t)h[1] << 16),
                                                 (uint32_t)h[2] | ((uint32_t)h[3] << 16));
    reinterpret_cast<uint2*>(lo)[i] = make_uint2((uint32_t)l[0] | ((uint32_t)l[1] << 16),
                                                 (uint32_t)l[2] | ((uint32_t)l[3] << 16));
}

// ============================ fused HMMA machinery ============================
#define LDA 136
#define REG_B 34816                 // one hi or lo tile (128 x 136 bf16)
#define SM_A  0
#define SM_B  (2 * REG_B)           // 69632
#define SM_T  (4 * REG_B)           // 139264
#define SM_BI (6 * REG_B)           // 208896
#define FUSED_SM (6 * REG_B + 1024) // 209920
#define GA_SM   (4 * REG_B + 1024)  // gemm_atom: A + B only

// load a full 128x128 hi/lo pair from gmem (row-major 16B segs) into smem region
__device__ __forceinline__ void load_tile_full(char* sm, int dst, const bf16* hi,
                                               const bf16* lo, int tid)
{
    const uint4* h4 = reinterpret_cast<const uint4*>(hi);
    const uint4* l4 = reinterpret_cast<const uint4*>(lo);
    #pragma unroll 4
    for (int q = 0; q < 8; q++) {
        int lin = q * 256 + tid;
        int row = lin >> 4, seg = lin & 15;
        *(uint4*)(sm + dst + row * 272 + seg * 16) = h4[lin];
        *(uint4*)(sm + dst + REG_B + row * 272 + seg * 16) = l4[lin];
    }
}
__device__ __forceinline__ void load_tile_bounded(char* sm, int dst, const bf16* hi,
                                                  const bf16* lo, int m0, int M, int tid)
{
    const uint4* h4 = reinterpret_cast<const uint4*>(hi);
    const uint4* l4 = reinterpret_cast<const uint4*>(lo);
    #pragma unroll 4
    for (int q = 0; q < 8; q++) {
        int lin = q * 256 + tid;
        int row = lin >> 4, seg = lin & 15;
        uint4 vh = make_uint4(0u,0u,0u,0u), vl = make_uint4(0u,0u,0u,0u);
        if (m0 + row < M) {
            size_t gi = (size_t)(m0 + row) * 16 + seg;
            vh = h4[gi]; vl = l4[gi];
        }
        *(uint4*)(sm + dst + row * 272 + seg * 16) = vh;
        *(uint4*)(sm + dst + REG_B + row * 272 + seg * 16) = vl;
    }
}

// one full 128x128x128 bf16x3 MMA stage from smem regions aoff/boff
__device__ __forceinline__ void do_mma_stage(uint32_t smb, uint32_t aoff, uint32_t boff,
                                             int lane, int warp_m, int warp_n,
                                             float acc[2][8][4])
{
    #pragma unroll
    for (int mt = 0; mt < 2; mt++)
        #pragma unroll
        for (int nt = 0; nt < 8; nt++)
            #pragma unroll
            for (int r = 0; r < 4; r++) acc[mt][nt][r] = 0.f;

    const int a_row  = warp_m * 32 + (lane & 15);
    const int a_koff = (lane >> 4) << 3;
    const uint32_t sa_hi = smb + aoff + ((uint32_t)a_row * LDA + a_koff) * 2;
    const uint32_t sa_lo = sa_hi + REG_B;
    const int b_n    = warp_n * 64 + (lane & 7) + ((lane >> 4) << 3);
    const int b_koff = ((lane >> 3) & 1) << 3;
    const uint32_t sb_hi = smb + boff + ((uint32_t)b_n * LDA + b_koff) * 2;
    const uint32_t sb_lo = sb_hi + REG_B;

    #pragma unroll 2
    for (int kt = 0; kt < 8; kt++) {
        const uint32_t kb = kt * 32;
        uint32_t ah[2][4], al[2][4];
        ldsm_x4(ah[0], sa_hi + kb);
        ldsm_x4(ah[1], sa_hi + 16 * LDA * 2 + kb);
        ldsm_x4(al[0], sa_lo + kb);
        ldsm_x4(al[1], sa_lo + 16 * LDA * 2 + kb);
        uint32_t bh[4][4], bl[4][4];
        #pragma unroll
        for (int p = 0; p < 4; p++) {
            ldsm_x4(bh[p], sb_hi + (uint32_t)p * 16 * LDA * 2 + kb);
            ldsm_x4(bl[p], sb_lo + (uint32_t)p * 16 * LDA * 2 + kb);
        }
        #pragma unroll
        for (int mt = 0; mt < 2; mt++)
            #pragma unroll
            for (int p = 0; p < 4; p++)
                #pragma unroll
                for (int hf = 0; hf < 2; hf++) {
                    int nt = p * 2 + hf;
                    mma_bf16(acc[mt][nt], ah[mt], bh[p][hf*2], bh[p][hf*2+1]);
                    mma_bf16(acc[mt][nt], ah[mt], bl[p][hf*2], bl[p][hf*2+1]);
                    mma_bf16(acc[mt][nt], al[mt], bh[p][hf*2], bh[p][hf*2+1]);
                }
    }
}

// silu(acc + bias?) -> split hi/lo -> smem T
template<bool BIAS>
__device__ __forceinline__ void store_T(char* sm, float acc[2][8][4], const float* sbias,
                                        int lane, int warp_m, int warp_n)
{
    #pragma unroll
    for (int mt = 0; mt < 2; mt++) {
        #pragma unroll
        for (int nt = 0; nt < 8; nt++) {
            int col = warp_n * 64 + nt * 8 + ((lane & 3) << 1);
            #pragma unroll
            for (int half = 0; half < 2; half++) {
                int r = warp_m * 32 + mt * 16 + (lane >> 2) + half * 8;
                float x0 = acc[mt][nt][half*2+0], x1 = acc[mt][nt][half*2+1];
                if (BIAS) { x0 += sbias[col]; x1 += sbias[col+1]; }
                x0 = x0 / (1.0f + expf(-x0));
                x1 = x1 / (1.0f + expf(-x1));
                bf16 h0, l0, h1, l1;
                split_bf16(x0, h0, l0); split_bf16(x1, h1, l1);
                uint32_t off = ((uint32_t)r * LDA + col) * 2;
                *(uint32_t*)(sm + SM_T + off) = (uint32_t)__bfloat16_as_ushort(h0)
                                              | ((uint32_t)__bfloat16_as_ushort(h1) << 16);
                *(uint32_t*)(sm + SM_T + REG_B + off) = (uint32_t)__bfloat16_as_ushort(l0)
                                              | ((uint32_t)__bfloat16_as_ushort(l1) << 16);
            }
        }
    }
}

template<bool BIAS>
__device__ __forceinline__ void store_out(float* out, float acc[2][8][4], const float* sbias,
                                          int m0, int M, int lane, int warp_m, int warp_n)
{
    #pragma unroll
    for (int mt = 0; mt < 2; mt++) {
        int r0 = m0 + warp_m * 32 + mt * 16 + (lane >> 2);
        #pragma unroll
        for (int nt = 0; nt < 8; nt++) {
            int col = warp_n * 64 + nt * 8 + ((lane & 3) << 1);
            float v[4];
            #pragma unroll
            for (int r = 0; r < 4; r++) {
                float x = acc[mt][nt][r];
                if (BIAS) x += sbias[col + (r & 1)];
                v[r] = x;
            }
            if (r0 < M)     *(float2*)&out[(size_t)r0 * NF + col]       = make_float2(v[0], v[1]);
            if (r0 + 8 < M) *(float2*)&out[(size_t)(r0 + 8) * NF + col] = make_float2(v[2], v[3]);
        }
    }
}

// ---------------- fused chain: out_c = silu(A@W(2c) [+b1]) @ W(2c+1) [+b2] ----------------
template<int NCH, bool BIAS>
__global__ void __launch_bounds__(256) fused_chain_k(
    const bf16* __restrict__ Ahi, const bf16* __restrict__ Alo,
    const bf16* __restrict__ W1hi, const bf16* __restrict__ W1lo,
    const bf16* __restrict__ W2hi, const bf16* __restrict__ W2lo,
    const bf16* __restrict__ W3hi, const bf16* __restrict__ W3lo,
    const bf16* __restrict__ W4hi, const bf16* __restrict__ W4lo,
    const float* __restrict__ bias1, const float* __restrict__ bias2,
    float* __restrict__ out1, float* __restrict__ out2, int M)
{
    extern __shared__ char sm[];
    const uint32_t smb = smem_u32(sm);
    const int tid  = threadIdx.x;
    const int lane = tid & 31;
    const int warp_m = (tid >> 5) >> 1;
    const int warp_n = (tid >> 5) & 1;
    const int m0   = blockIdx.x * 128;

    float* sb1 = (float*)(sm + SM_BI);
    float* sb2 = (float*)(sm + SM_BI + 512);
    if (BIAS && tid < 128) { sb1[tid] = bias1[tid]; sb2[tid] = bias2[tid]; }

    load_tile_bounded(sm, SM_A, Ahi, Alo, m0, M, tid);
    load_tile_full(sm, SM_B, W1hi, W1lo, tid);
    __syncthreads();

    float acc[2][8][4];
    // stage 1: T = silu(A@W1 [+b1])
    do_mma_stage(smb, SM_A, SM_B, lane, warp_m, warp_n, acc);
    store_T<BIAS>(sm, acc, sb1, lane, warp_m, warp_n);
    __syncthreads();
    load_tile_full(sm, SM_B, W2hi, W2lo, tid);
    __syncthreads();
    // stage 2: out1 = T@W2 [+b2]
    do_mma_stage(smb, SM_T, SM_B, lane, warp_m, warp_n, acc);
    store_out<BIAS>(out1, acc, sb2, m0, M, lane, warp_m, warp_n);

    if (NCH == 2) {
        __syncthreads();
        load_tile_full(sm, SM_B, W3hi, W3lo, tid);
        __syncthreads();
        do_mma_stage(smb, SM_A, SM_B, lane, warp_m, warp_n, acc);
        store_T<false>(sm, acc, sb1, lane, warp_m, warp_n);
        __syncthreads();
        load_tile_full(sm, SM_B, W4hi, W4lo, tid);
        __syncthreads();
        do_mma_stage(smb, SM_T, SM_B, lane, warp_m, warp_n, acc);
        store_out<false>(out2, acc, sb2, m0, M, lane, warp_m, warp_n);
    }
}

// ---------------- g = force@euW fused with atom += sum_d force*g ----------------
__global__ void __launch_bounds__(256) gemm_atom_k(
    const bf16* __restrict__ Fhi, const bf16* __restrict__ Flo,
    const bf16* __restrict__ Whi, const bf16* __restrict__ Wlo,
    const float* __restrict__ force, float* __restrict__ atom, int M)
{
    extern __shared__ char sm[];
    const uint32_t smb = smem_u32(sm);
    const int tid  = threadIdx.x;
    const int lane = tid & 31;
    const int warp_m = (tid >> 5) >> 1;
    const int warp_n = (tid >> 5) & 1;
    const int m0   = blockIdx.x * 128;

    load_tile_bounded(sm, SM_A, Fhi, Flo, m0, M, tid);
    load_tile_full(sm, SM_B, Whi, Wlo, tid);
    __syncthreads();

    float acc[2][8][4];
    do_mma_stage(smb, SM_A, SM_B, lane, warp_m, warp_n, acc);

    #pragma unroll
    for (int mt = 0; mt < 2; mt++) {
        #pragma unroll
        for (int half = 0; half < 2; half++) {
            int r = m0 + warp_m * 32 + mt * 16 + (lane >> 2) + half * 8;
            if (r >= M) continue;
            int n = r / 3;
            #pragma unroll
            for (int nt = 0; nt < 8; nt++) {
                int col = warp_n * 64 + nt * 8 + ((lane & 3) << 1);
                float2 f = *(const float2*)&force[(size_t)r * NF + col];
                atomicAdd(&atom[(size_t)n * NF + col],     acc[mt][nt][half*2+0] * f.x);
                atomicAdd(&atom[(size_t)n * NF + col + 1], acc[mt][nt][half*2+1] * f.y);
            }
        }
    }
}

// ---------------- init: atom = node_emb[z] ----------------
__global__ void init_atom_k(const int* __restrict__ z, const float* __restrict__ emb,
                            float* __restrict__ atom)
{
    int idx = blockIdx.x * blockDim.x + threadIdx.x;
    int n = idx >> 7, f = idx & 127;
    atom[idx] = emb[(size_t)z[n] * NF + f];
}

// ---------------- edge embedding ----------------
__global__ void edge_embed_k(const float* __restrict__ pos, const int* __restrict__ ei,
                             float* __restrict__ dist, float* __restrict__ dir)
{
    int e = blockIdx.x * blockDim.x + threadIdx.x;
    if (e >= N_EDGES) return;
    int i = ei[e], j = ei[N_EDGES + e];
    float dx = pos[j*3+0] - pos[i*3+0];
    float dy = pos[j*3+1] - pos[i*3+1];
    float dz = pos[j*3+2] - pos[i*3+2];
    float d = sqrtf(dx*dx + dy*dy + dz*dz + 1e-12f);
    float inv = 1.0f / d;
    dir[e*3+0] = dx*inv; dir[e*3+1] = dy*inv; dir[e*3+2] = dz*inv;
    float fc = (d < CUTOFF_R) ? 0.5f * (cosf(3.14159265358979323846f * d / CUTOFF_R) + 1.0f) : 0.0f;
    const float inv_w = 1.0f / (CUTOFF_R / NB);
    #pragma unroll
    for (int b = 0; b < NB; b++) {
        float c = CUTOFF_R * (float)b / (float)(NB - 1);
        float t = (d - c) * inv_w;
        dist[(size_t)e*NB + b] = expf(-t*t) * fc;
    }
}

// ---------------- msg: hi/lo out + atom segsum ----------------
__global__ void msg_k2(const float* __restrict__ h, const float* __restrict__ dist,
                       const int* __restrict__ ei, const float* __restrict__ meW,
                       bf16* __restrict__ mhi, bf16* __restrict__ mlo,
                       float* __restrict__ atom)
{
    __shared__ float sW[NB * NF];
    __shared__ float sd[32 * NB];
    int f = threadIdx.x;
    #pragma unroll
    for (int b = 0; b < NB; b++) sW[b*NF + f] = meW[b*NF + f];
    int e0 = blockIdx.x * 32;
    for (int q = f; q < 32 * NB; q += NF) sd[q] = dist[(size_t)e0 * NB + q];
    __syncthreads();
    #pragma unroll 2
    for (int t = 0; t < 32; t++) {
        int e = e0 + t;
        int i = ei[e], j = ei[N_EDGES + e];
        float me = 0.f;
        #pragma unroll
        for (int b = 0; b < NB; b++) me = fmaf(sd[t*NB + b], sW[b*NF + f], me);
        float m = me * h[(size_t)i*NF + f] * h[(size_t)j*NF + f];
        bf16 hb, lb; split_bf16(m, hb, lb);
        mhi[(size_t)e*NF + f] = hb;
        mlo[(size_t)e*NF + f] = lb;
        atomicAdd(&atom[(size_t)i*NF + f], m);
    }
}

// ---------------- fdelta += segsum(p1*dir + p2*force[j], i) ----------------
__global__ void scatter_force_k(const float* __restrict__ p1, const float* __restrict__ p2,
                                const float* __restrict__ dir, const float* __restrict__ force,
                                const int* __restrict__ ei, float* __restrict__ fdelta)
{
    int f = threadIdx.x;
    int e0 = blockIdx.x * 8;
    for (int t = 0; t < 8; t++) {
        int e = e0 + t;
        int i = ei[e], j = ei[N_EDGES + e];
        float v1 = p1[(size_t)e*NF + f];
        float v2 = p2[(size_t)e*NF + f];
        float dx = dir[e*3+0], dy = dir[e*3+1], dz = dir[e*3+2];
        const float* fj = &force[(size_t)j * 3 * NF];
        float* fd = &fdelta[(size_t)i * 3 * NF];
        atomicAdd(&fd[0*NF + f], fmaf(v1, dx, v2 * fj[0*NF + f]));
        atomicAdd(&fd[1*NF + f], fmaf(v1, dy, v2 * fj[1*NF + f]));
        atomicAdd(&fd[2*NF + f], fmaf(v1, dz, v2 * fj[2*NF + f]));
    }
}

// ---------------- force += fdelta; fdelta=0; emit hi/lo ----------------
__global__ void force_update_k2(float* __restrict__ force, float* __restrict__ fdelta,
                                bf16* __restrict__ fhi, bf16* __restrict__ flo)
{
    int idx = blockIdx.x * blockDim.x + threadIdx.x;
    float v = force[idx] + fdelta[idx];
    force[idx] = v;
    fdelta[idx] = 0.f;
    bf16 hb, lb; split_bf16(v, hb, lb);
    fhi[idx] = hb; flo[idx] = lb;
}

// ---------------- host ----------------
extern "C" void kernel_launch(void* const* d_in, const int* in_sizes, int n_in,
                              void* d_out, int out_size)
{
    const int*   z        = (const int*)  d_in[0];
    const float* pos      = (const float*)d_in[1];
    const int*   ei       = (const int*)  d_in[4];
    const float* node_emb = (const float*)d_in[5];
    const float* mnp_W1   = (const float*)d_in[6];
    const float* mnp_b1   = (const float*)d_in[7];
    const float* mnp_W2   = (const float*)d_in[8];
    const float* mnp_b2   = (const float*)d_in[9];
    const float* me_W     = (const float*)d_in[10];
    const float* em1_W1   = (const float*)d_in[11];
    const float* em1_W2   = (const float*)d_in[12];
    const float* em2_W1   = (const float*)d_in[13];
    const float* em2_W2   = (const float*)d_in[14];
    const float* eu_W     = (const float*)d_in[15];

    float* atom = (float*)d_out;
    float* force;

    float *dist, *dir, *h, *p1, *p2, *fdelta, *force_fb;
    bf16 *bhi1, *blo1, *bhi2, *blo2, *whi, *wlo;
    cudaGetSymbolAddress((void**)&dist,     g_dist);
    cudaGetSymbolAddress((void**)&dir,      g_dir);
    cudaGetSymbolAddress((void**)&h,        g_h);
    cudaGetSymbolAddress((void**)&p1,       g_p1);
    cudaGetSymbolAddress((void**)&p2,       g_p2);
    cudaGetSymbolAddress((void**)&fdelta,   g_fdelta);
    cudaGetSymbolAddress((void**)&force_fb, g_force_fb);
    cudaGetSymbolAddress((void**)&bhi1, g_bhi1);
    cudaGetSymbolAddress((void**)&blo1, g_blo1);
    cudaGetSymbolAddress((void**)&bhi2, g_bhi2);
    cudaGetSymbolAddress((void**)&blo2, g_blo2);
    cudaGetSymbolAddress((void**)&whi,  g_whi);
    cudaGetSymbolAddress((void**)&wlo,  g_wlo);

    if (out_size >= N_NODES * (NF + 3 * NF)) force = atom + (size_t)N_NODES * NF;
    else                                     force = force_fb;

    cudaFuncSetAttribute(fused_chain_k<1, true >, cudaFuncAttributeMaxDynamicSharedMemorySize, FUSED_SM);
    cudaFuncSetAttribute(fused_chain_k<2, false>, cudaFuncAttributeMaxDynamicSharedMemorySize, FUSED_SM);
    cudaFuncSetAttribute(gemm_atom_k, cudaFuncAttributeMaxDynamicSharedMemorySize, GA_SM);
    cudaFuncSetAttribute(prep_w_k, cudaFuncAttributeMaxDynamicSharedMemorySize, PREP_SM);

    prep_w_k<<<3, 256, PREP_SM>>>(mnp_W1, whi + 0*16384, wlo + 0*16384);
    prep_w_k<<<3, 256, PREP_SM>>>(mnp_W2, whi + 1*16384, wlo + 1*16384);
    prep_w_k<<<3, 256, PREP_SM>>>(em1_W1, whi + 2*16384, wlo + 2*16384);
    prep_w_k<<<3, 256, PREP_SM>>>(em1_W2, whi + 3*16384, wlo + 3*16384);
    prep_w_k<<<3, 256, PREP_SM>>>(em2_W1, whi + 4*16384, wlo + 4*16384);
    prep_w_k<<<3, 256, PREP_SM>>>(em2_W2, whi + 5*16384, wlo + 5*16384);
    prep_w_k<<<3, 256, PREP_SM>>>(eu_W,   whi + 6*16384, wlo + 6*16384);

    cudaMemsetAsync(force,  0, (size_t)N_NODES * 3 * NF * sizeof(float), 0);
    cudaMemsetAsync(fdelta, 0, (size_t)N_NODES * 3 * NF * sizeof(float), 0);

    init_atom_k<<<(N_NODES * NF) / 256, 256>>>(z, node_emb, atom);
    edge_embed_k<<<(N_EDGES + 255) / 256, 256>>>(pos, ei, dist, dir);

    const int GN  = (N_NODES + 127) / 128;       // 79
    const int GE  = N_EDGES / 128;               // 1250
    const int GF3 = (N_NODES * 3 + 127) / 128;   // 235

    for (int l = 0; l < NLAYERS; l++) {
        const bf16* Whi = whi + (size_t)l * 7 * 16384;
        const bf16* Wlo = wlo + (size_t)l * 7 * 16384;
        const float* b1 = mnp_b1 + (size_t)l * NF;
        const float* b2 = mnp_b2 + (size_t)l * NF;
        const float* mW = me_W   + (size_t)l * NB * NF;

        // atom -> hi/lo
        conv_k<<<(N_NODES * NF / 4 + 255) / 256, 256>>>(atom, bhi1, blo1, N_NODES * NF / 4);

        // h = silu(atom@W1+b1)@W2+b2 (fused chain)
        fused_chain_k<1, true><<<GN, 256, FUSED_SM>>>(
            bhi1, blo1,
            Whi + 0*16384, Wlo + 0*16384, Whi + 1*16384, Wlo + 1*16384,
            nullptr, nullptr, nullptr, nullptr,
            b1, b2, h, nullptr, N_NODES);

        // msg (hi/lo) + atom segsum
        msg_k2<<<N_EDGES / 32, NF>>>(h, dist, ei, mW, bhi1, blo1, atom);

        // p1 = silu(msg@e11)@e12 ; p2 = silu(msg@e21)@e22 (one fused kernel)
        fused_chain_k<2, false><<<GE, 256, FUSED_SM>>>(
            bhi1, blo1,
            Whi + 2*16384, Wlo + 2*16384, Whi + 3*16384, Wlo + 3*16384,
            Whi + 4*16384, Wlo + 4*16384, Whi + 5*16384, Wlo + 5*16384,
            nullptr, nullptr, p1, p2, N_EDGES);

        // scatter + force update (emits force hi/lo)
        scatter_force_k<<<N_EDGES / 8, NF>>>(p1, p2, dir, force, ei, fdelta);
        force_update_k2<<<(N_NODES * 3 * NF) / 256, 256>>>(force, fdelta, bhi2, blo2);

        // atom += sum_d force * (force@euW)  (fused GEMM + reduction)
        gemm_atom_k<<<GF3, 256, GA_SM>>>(bhi2, blo2, Whi + 6*16384, Wlo + 6*16384,
                                         force, atom, N_NODES * 3);
    }
}